// round 1
// baseline (speedup 1.0000x reference)
#include <cuda_runtime.h>

// Problem-fixed shapes (from reference setup_inputs)
#define BATCH 8192
#define TLEN  256
#define HID   32

// Scratch: decoder pre-gates per batch element (i,f,g,o) — __device__ global, no allocs
__device__ float g_pre[BATCH * 4];

// ---------- helpers ----------
static __device__ __forceinline__ unsigned long long ffma2(unsigned long long a,
                                                           unsigned long long b,
                                                           unsigned long long c) {
    unsigned long long d;
    asm("fma.rn.f32x2 %0, %1, %2, %3;" : "=l"(d) : "l"(a), "l"(b), "l"(c));
    return d;
}
static __device__ __forceinline__ unsigned long long pack2(float lo, float hi) {
    unsigned long long d;
    asm("mov.b64 %0, {%1, %2};" : "=l"(d) : "f"(lo), "f"(hi));
    return d;
}
static __device__ __forceinline__ float hadd2(unsigned long long a) {
    float lo, hi;
    asm("mov.b64 {%0, %1}, %2;" : "=f"(lo), "=f"(hi) : "l"(a));
    return lo + hi;
}
static __device__ __forceinline__ float sigmoid_f(float x) {
    return __fdividef(1.0f, 1.0f + __expf(-x));
}
static __device__ __forceinline__ float tanh_f(float x) {
    return __fdividef(2.0f, 1.0f + __expf(-2.0f * x)) - 1.0f;
}

// ---------- encoder: one warp per batch element, lane = hidden unit ----------
__global__ void __launch_bounds__(128, 2) enc_kernel(
    const float* __restrict__ x,        // [B, T, 1]
    const float* __restrict__ eWih,     // [128, 1]
    const float* __restrict__ eWhh,     // [128, 32]
    const float* __restrict__ ebih,     // [128]
    const float* __restrict__ ebhh,     // [128]
    const float* __restrict__ dWih,     // [4, 32]
    const float* __restrict__ dbih,     // [4]
    const float* __restrict__ dbhh)     // [4]
{
    __shared__ __align__(16) float hbuf[4][2][HID];  // 4 warps/block, double-buffered h

    const int lane = threadIdx.x & 31;
    const int w    = threadIdx.x >> 5;
    const int b    = blockIdx.x * 4 + w;

    // Register-resident W_hh rows for this lane's hidden unit, as f32x2 pairs.
    // Gate g row = g*32 + lane, 32 floats = 8 x ulonglong2 (each = 2 packed pairs).
    ulonglong2 wr[4][8];
#pragma unroll
    for (int g = 0; g < 4; g++) {
        const ulonglong2* row = reinterpret_cast<const ulonglong2*>(eWhh + (g * HID + lane) * HID);
#pragma unroll
        for (int j = 0; j < 8; j++) wr[g][j] = row[j];
    }

    float bias[4], wx[4];
#pragma unroll
    for (int g = 0; g < 4; g++) {
        bias[g] = ebih[g * HID + lane] + ebhh[g * HID + lane];
        wx[g]   = eWih[g * HID + lane];  // IN == 1
    }

    float h = 0.0f, c = 0.0f;
    hbuf[w][0][lane] = 0.0f;
    __syncwarp();

    const float* xs = x + (long)b * TLEN;
    float xl_cur = xs[lane];
    int p = 0;

#pragma unroll 1
    for (int t0 = 0; t0 < TLEN; t0 += 32) {
        float xl_next = (t0 + 32 < TLEN) ? xs[t0 + 32 + lane] : 0.0f;

#pragma unroll 4
        for (int dt = 0; dt < 32; dt++) {
            float xv = __shfl_sync(0xffffffffu, xl_cur, dt);

            unsigned long long ai = pack2(fmaf(xv, wx[0], bias[0]), 0.0f);
            unsigned long long af = pack2(fmaf(xv, wx[1], bias[1]), 0.0f);
            unsigned long long ag = pack2(fmaf(xv, wx[2], bias[2]), 0.0f);
            unsigned long long ao = pack2(fmaf(xv, wx[3], bias[3]), 0.0f);

            const ulonglong2* hb = reinterpret_cast<const ulonglong2*>(hbuf[w][p]);
#pragma unroll
            for (int j = 0; j < 8; j++) {
                ulonglong2 hp = hb[j];   // broadcast LDS.128
                ai = ffma2(wr[0][j].x, hp.x, ai);
                ai = ffma2(wr[0][j].y, hp.y, ai);
                af = ffma2(wr[1][j].x, hp.x, af);
                af = ffma2(wr[1][j].y, hp.y, af);
                ag = ffma2(wr[2][j].x, hp.x, ag);
                ag = ffma2(wr[2][j].y, hp.y, ag);
                ao = ffma2(wr[3][j].x, hp.x, ao);
                ao = ffma2(wr[3][j].y, hp.y, ao);
            }

            float ig = sigmoid_f(hadd2(ai));
            float fg = sigmoid_f(hadd2(af));
            float gg = tanh_f(hadd2(ag));
            float og = sigmoid_f(hadd2(ao));

            c = fg * c + ig * gg;
            h = og * tanh_f(c);

            hbuf[w][p ^ 1][lane] = h;
            __syncwarp();
            p ^= 1;
        }
        xl_cur = xl_next;
    }

    // Decoder pre-gates: pre[j] = h . dec_W_ih[j] + dec_b_ih[j] + dec_b_hh[j]
    float v0 = h * dWih[0 * HID + lane];
    float v1 = h * dWih[1 * HID + lane];
    float v2 = h * dWih[2 * HID + lane];
    float v3 = h * dWih[3 * HID + lane];
#pragma unroll
    for (int off = 16; off >= 1; off >>= 1) {
        v0 += __shfl_xor_sync(0xffffffffu, v0, off);
        v1 += __shfl_xor_sync(0xffffffffu, v1, off);
        v2 += __shfl_xor_sync(0xffffffffu, v2, off);
        v3 += __shfl_xor_sync(0xffffffffu, v3, off);
    }
    if (lane == 0) {
        float4 r;
        r.x = v0 + dbih[0] + dbhh[0];
        r.y = v1 + dbih[1] + dbhh[1];
        r.z = v2 + dbih[2] + dbhh[2];
        r.w = v3 + dbih[3] + dbhh[3];
        reinterpret_cast<float4*>(g_pre)[b] = r;
    }
}

// ---------- decoder: one thread per batch element, scalar recurrence ----------
__global__ void __launch_bounds__(256) dec_kernel(
    const float* __restrict__ dWhh,   // [4, 1]
    float* __restrict__ out)          // [B, T, 1]
{
    const int b = blockIdx.x * blockDim.x + threadIdx.x;
    if (b >= BATCH) return;

    const float4 pre = reinterpret_cast<const float4*>(g_pre)[b];
    const float wi = dWhh[0], wf = dWhh[1], wg = dWhh[2], wo = dWhh[3];

    float h = 0.0f, c = 0.0f;
    float4* outv = reinterpret_cast<float4*>(out + (long)b * TLEN);

#pragma unroll 1
    for (int t = 0; t < TLEN; t += 4) {
        float4 ov;
        float* op = &ov.x;
#pragma unroll
        for (int k = 0; k < 4; k++) {
            float ig = sigmoid_f(pre.x + wi * h);
            float fg = sigmoid_f(pre.y + wf * h);
            float gg = tanh_f(pre.z + wg * h);
            float og = sigmoid_f(pre.w + wo * h);
            c = fg * c + ig * gg;
            h = og * tanh_f(c);
            op[k] = h;
        }
        outv[t >> 2] = ov;
    }
}

// ---------- launch ----------
extern "C" void kernel_launch(void* const* d_in, const int* in_sizes, int n_in,
                              void* d_out, int out_size) {
    const float* x     = (const float*)d_in[0];
    const float* eWih  = (const float*)d_in[1];
    const float* eWhh  = (const float*)d_in[2];
    const float* ebih  = (const float*)d_in[3];
    const float* ebhh  = (const float*)d_in[4];
    const float* dWih  = (const float*)d_in[5];
    const float* dWhh  = (const float*)d_in[6];
    const float* dbih  = (const float*)d_in[7];
    const float* dbhh  = (const float*)d_in[8];
    float* out = (float*)d_out;

    enc_kernel<<<BATCH / 4, 128>>>(x, eWih, eWhh, ebih, ebhh, dWih, dbih, dbhh);
    dec_kernel<<<BATCH / 256, 256>>>(dWhh, out);
}

// round 5
// speedup vs baseline: 1.1128x; 1.1128x over previous
#include <cuda_runtime.h>

// Problem-fixed shapes (from reference setup_inputs)
#define BATCH 8192
#define TLEN  256
#define HID   32

// Scratch: decoder pre-gates per batch element (i,f,g,o) — __device__ global, no allocs
__device__ float g_pre[BATCH * 4];

// ---------- helpers ----------
static __device__ __forceinline__ unsigned long long ffma2(unsigned long long a,
                                                           unsigned long long b,
                                                           unsigned long long c) {
    unsigned long long d;
    asm("fma.rn.f32x2 %0, %1, %2, %3;" : "=l"(d) : "l"(a), "l"(b), "l"(c));
    return d;
}
static __device__ __forceinline__ unsigned long long pack2(float lo, float hi) {
    unsigned long long d;
    asm("mov.b64 %0, {%1, %2};" : "=l"(d) : "f"(lo), "f"(hi));
    return d;
}
static __device__ __forceinline__ float hadd2(unsigned long long a) {
    float lo, hi;
    asm("mov.b64 {%0, %1}, %2;" : "=f"(lo), "=f"(hi) : "l"(a));
    return lo + hi;
}
static __device__ __forceinline__ float sigmoid_fast(float x) {
    return __fdividef(1.0f, 1.0f + __expf(-x));
}
static __device__ __forceinline__ float tanh_f(float x) {
    // 2/(1+e^-2x) - 1 : mul, ex2, add, rcp, fma(2r-1)  (2 MUFU, 3 fma-pipe)
    float r = __fdividef(1.0f, 1.0f + __expf(-2.0f * x));
    return fmaf(2.0f, r, -1.0f);
}

// ---------- encoder: one warp per batch element, lane = hidden unit ----------
__global__ void __launch_bounds__(128, 3) enc_kernel(
    const float* __restrict__ x,        // [B, T, 1]
    const float* __restrict__ eWih,     // [128, 1]
    const float* __restrict__ eWhh,     // [128, 32]
    const float* __restrict__ ebih,     // [128]
    const float* __restrict__ ebhh,     // [128]
    const float* __restrict__ dWih,     // [4, 32]
    const float* __restrict__ dbih,     // [4]
    const float* __restrict__ dbhh)     // [4]
{
    __shared__ __align__(16) float hbuf[4][2][HID];  // 4 warps/block, double-buffered h

    const int lane = threadIdx.x & 31;
    const int w    = threadIdx.x >> 5;
    const int b    = blockIdx.x * 4 + w;

    // Register-resident W_hh rows for this lane's hidden unit, as f32x2 pairs.
    // Gate g row = g*32 + lane, 32 floats = 8 x ulonglong2 (each = 2 packed pairs).
    ulonglong2 wr[4][8];
#pragma unroll
    for (int g = 0; g < 4; g++) {
        const ulonglong2* row = reinterpret_cast<const ulonglong2*>(eWhh + (g * HID + lane) * HID);
#pragma unroll
        for (int j = 0; j < 8; j++) wr[g][j] = row[j];
    }

    float bias[4], wx[4];
#pragma unroll
    for (int g = 0; g < 4; g++) {
        bias[g] = ebih[g * HID + lane] + ebhh[g * HID + lane];
        wx[g]   = eWih[g * HID + lane];  // IN == 1
    }

    float h = 0.0f, c = 0.0f;
    hbuf[w][0][lane] = 0.0f;
    __syncwarp();

    const float* xs = x + (long)b * TLEN;
    float xl_cur = xs[lane];
    int p = 0;

#pragma unroll 1
    for (int t0 = 0; t0 < TLEN; t0 += 32) {
        float xl_next = (t0 + 32 < TLEN) ? xs[t0 + 32 + lane] : 0.0f;

#pragma unroll 4
        for (int dt = 0; dt < 32; dt++) {
            float xv = __shfl_sync(0xffffffffu, xl_cur, dt);

            unsigned long long ai = pack2(fmaf(xv, wx[0], bias[0]), 0.0f);
            unsigned long long af = pack2(fmaf(xv, wx[1], bias[1]), 0.0f);
            unsigned long long ag = pack2(fmaf(xv, wx[2], bias[2]), 0.0f);
            unsigned long long ao = pack2(fmaf(xv, wx[3], bias[3]), 0.0f);

            const ulonglong2* hb = reinterpret_cast<const ulonglong2*>(hbuf[w][p]);
#pragma unroll
            for (int j = 0; j < 8; j++) {
                ulonglong2 hp = hb[j];   // broadcast LDS.128
                ai = ffma2(wr[0][j].x, hp.x, ai);
                ai = ffma2(wr[0][j].y, hp.y, ai);
                af = ffma2(wr[1][j].x, hp.x, af);
                af = ffma2(wr[1][j].y, hp.y, af);
                ag = ffma2(wr[2][j].x, hp.x, ag);
                ag = ffma2(wr[2][j].y, hp.y, ag);
                ao = ffma2(wr[3][j].x, hp.x, ao);
                ao = ffma2(wr[3][j].y, hp.y, ao);
            }

            float ig = sigmoid_fast(hadd2(ai));
            float fg = sigmoid_fast(hadd2(af));
            float gg = tanh_f(hadd2(ag));
            float og = sigmoid_fast(hadd2(ao));

            c = fg * c + ig * gg;
            h = og * tanh_f(c);

            hbuf[w][p ^ 1][lane] = h;
            __syncwarp();
            p ^= 1;
        }
        xl_cur = xl_next;
    }

    // Decoder pre-gates: pre[j] = h . dec_W_ih[j] + dec_b_ih[j] + dec_b_hh[j]
    float v0 = h * dWih[0 * HID + lane];
    float v1 = h * dWih[1 * HID + lane];
    float v2 = h * dWih[2 * HID + lane];
    float v3 = h * dWih[3 * HID + lane];
#pragma unroll
    for (int off = 16; off >= 1; off >>= 1) {
        v0 += __shfl_xor_sync(0xffffffffu, v0, off);
        v1 += __shfl_xor_sync(0xffffffffu, v1, off);
        v2 += __shfl_xor_sync(0xffffffffu, v2, off);
        v3 += __shfl_xor_sync(0xffffffffu, v3, off);
    }
    if (lane == 0) {
        float4 r;
        r.x = v0 + dbih[0] + dbhh[0];
        r.y = v1 + dbih[1] + dbhh[1];
        r.z = v2 + dbih[2] + dbhh[2];
        r.w = v3 + dbih[3] + dbhh[3];
        reinterpret_cast<float4*>(g_pre)[b] = r;
    }
}

// ---------- decoder: one thread per batch element, scalar recurrence ----------
// 64 threads/block x 128 blocks: spread the MUFU-bound work across ~128 SMs.
__global__ void __launch_bounds__(64) dec_kernel(
    const float* __restrict__ dWhh,   // [4, 1]
    float* __restrict__ out)          // [B, T, 1]
{
    const int b = blockIdx.x * blockDim.x + threadIdx.x;
    if (b >= BATCH) return;

    const float4 pre = reinterpret_cast<const float4*>(g_pre)[b];
    const float wi = dWhh[0], wf = dWhh[1], wg = dWhh[2], wo = dWhh[3];

    float h = 0.0f, c = 0.0f;
    float4* outv = reinterpret_cast<float4*>(out + (long)b * TLEN);

#pragma unroll 1
    for (int t = 0; t < TLEN; t += 4) {
        float4 ov;
        float* op = &ov.x;
#pragma unroll
        for (int k = 0; k < 4; k++) {
            float ig = sigmoid_fast(pre.x + wi * h);
            float fg = sigmoid_fast(pre.y + wf * h);
            float gg = tanh_f(pre.z + wg * h);
            float og = sigmoid_fast(pre.w + wo * h);
            c = fg * c + ig * gg;
            h = og * tanh_f(c);
            op[k] = h;
        }
        outv[t >> 2] = ov;
    }
}

// ---------- launch ----------
extern "C" void kernel_launch(void* const* d_in, const int* in_sizes, int n_in,
                              void* d_out, int out_size) {
    const float* x     = (const float*)d_in[0];
    const float* eWih  = (const float*)d_in[1];
    const float* eWhh  = (const float*)d_in[2];
    const float* ebih  = (const float*)d_in[3];
    const float* ebhh  = (const float*)d_in[4];
    const float* dWih  = (const float*)d_in[5];
    const float* dWhh  = (const float*)d_in[6];
    const float* dbih  = (const float*)d_in[7];
    const float* dbhh  = (const float*)d_in[8];
    float* out = (float*)d_out;

    enc_kernel<<<BATCH / 4, 128>>>(x, eWih, eWhh, ebih, ebhh, dWih, dbih, dbhh);
    dec_kernel<<<BATCH / 64, 64>>>(dWhh, out);
}